// round 14
// baseline (speedup 1.0000x reference)
#include <cuda_runtime.h>
#include <cuda_bf16.h>
#include <cstdint>

// S4D via warp-level mma.sync bf16 (compute_103-safe; tcgen05 unavailable in
// this toolchain). K[h, 32m + r] = Re( sum_n V[h,n,m] * U[h,n,r] ),
//   V = w32^m (m=0..63), U = cm*w^r (r=0..31), w = exp(dtA).
// Per h: D[64x32] = A[64x128] @ B[128x32] (K = [Re | Im], B Im negated),
// bf16 2-way split, 3 products (AhBh + AlBh + AhBl), fp32 accum.
//
// R14: transcendentals hoisted to a separate precompute kernel (device-global
// params); main kernel = load params -> short staging recurrences -> MMA.
// 256 threads: staging chains halve, MMA n-tiles split across warp pairs.

#define RSE   136                    // tile row stride in bf16 elems (272 B)
#define OFF_AH 0                     // 64 x 272B = 17408
#define OFF_AL 17408
#define OFF_BH 34816                 // 32 x 272B = 8704
#define OFF_BL 43520
#define SMEM_TOTAL 52224

typedef uint32_t u32;

#define NPAR 65536                   // 1024 h * 64 n
__device__ float2 g_cm[NPAR], g_w1[NPAR], g_w8[NPAR], g_w16[NPAR];
__device__ float2 g_w32[NPAR], g_w512[NPAR], g_w1024[NPAR];

__device__ __forceinline__ float2 cmul(float2 a, float2 b) {
    return make_float2(a.x * b.x - a.y * b.y, a.x * b.y + a.y * b.x);
}

// ---- precompute: per (h,n) constants; precise transcendentals + squarings ----
extern "C" __global__ void __launch_bounds__(256)
s4d_pre(const float* __restrict__ log_dt, const float* __restrict__ C,
        const float* __restrict__ A)
{
    int i = blockIdx.x * blockDim.x + threadIdx.x;
    if (i >= NPAR) return;
    int h = i >> 6, n = i & 63;

    float dt  = expf(log_dt[h]);
    float ar  = A[2 * n], ai = A[2 * n + 1];
    float dre = dt * ar, dim = dt * ai;

    float e1 = expf(dre); float s1, c1; sincosf(dim, &s1, &c1);
    float2 w1 = make_float2(e1 * c1, e1 * s1);

    float inv = 1.0f / (ar * ar + ai * ai);
    float nr = w1.x - 1.0f, ni = w1.y;
    float qdr = (nr * ar + ni * ai) * inv;
    float qdi = (ni * ar - nr * ai) * inv;
    float cr = C[2 * i], ci = C[2 * i + 1];
    g_cm[i] = make_float2(2.0f * (cr * qdr - ci * qdi),
                          2.0f * (cr * qdi + ci * qdr));
    g_w1[i] = w1;

    float2 w2   = cmul(w1, w1);
    float2 w4   = cmul(w2, w2);
    float2 w8   = cmul(w4, w4);
    float2 w16  = cmul(w8, w8);
    float2 w32  = cmul(w16, w16);
    float2 w64  = cmul(w32, w32);
    float2 w128 = cmul(w64, w64);
    float2 w256 = cmul(w128, w128);
    float2 w512 = cmul(w256, w256);
    g_w8[i]    = w8;
    g_w16[i]   = w16;
    g_w32[i]   = w32;
    g_w512[i]  = w512;
    g_w1024[i] = cmul(w512, w512);
}

__device__ __forceinline__ u32 smem_u32(const void* p) {
    u32 a;
    asm("{ .reg .u64 t; cvta.to.shared.u64 t, %1; cvt.u32.u64 %0, t; }"
        : "=r"(a) : "l"(p));
    return a;
}
__device__ __forceinline__ void ldsm4(u32 r[4], u32 addr) {
    asm volatile("ldmatrix.sync.aligned.m8n8.x4.shared.b16 {%0,%1,%2,%3}, [%4];"
                 : "=r"(r[0]), "=r"(r[1]), "=r"(r[2]), "=r"(r[3]) : "r"(addr));
}
__device__ __forceinline__ void mma_bf16(float d[4], const u32 a[4],
                                         u32 b0, u32 b1) {
    asm volatile(
        "mma.sync.aligned.m16n8k16.row.col.f32.bf16.bf16.f32 "
        "{%0,%1,%2,%3}, {%4,%5,%6,%7}, {%8,%9}, {%0,%1,%2,%3};"
        : "+f"(d[0]), "+f"(d[1]), "+f"(d[2]), "+f"(d[3])
        : "r"(a[0]), "r"(a[1]), "r"(a[2]), "r"(a[3]), "r"(b0), "r"(b1));
}
__device__ __forceinline__ __nv_bfloat16 bfh(float x) {
    return __float2bfloat16_rn(x);
}

extern "C" __global__ void __launch_bounds__(256)
s4d_hmma(float* __restrict__ out)
{
    extern __shared__ __align__(256) char sm[];
    const u32 sb  = smem_u32(sm);
    const int tid = threadIdx.x, wid = tid >> 5, lane = tid & 31;
    const int h   = blockIdx.x;

    __nv_bfloat16* AH = (__nv_bfloat16*)(sm + OFF_AH);
    __nv_bfloat16* AL = (__nv_bfloat16*)(sm + OFF_AL);
    __nv_bfloat16* BH = (__nv_bfloat16*)(sm + OFF_BH);
    __nv_bfloat16* BL = (__nv_bfloat16*)(sm + OFF_BL);

    // ---- staging: thread = (n, quarter q) ----
    const int n = tid & 63, q = tid >> 6;
    const int pi = h * 64 + n;

    // A (V = w32^m): q covers m in [16q, 16q+16)
    {
        float2 w32 = g_w32[pi];
        float2 z = make_float2(1.0f, 0.0f);
        if (q & 1) z = g_w512[pi];
        if (q & 2) z = (q & 1) ? cmul(g_w512[pi], g_w1024[pi]) : g_w1024[pi];
        int m = q * 16;
#pragma unroll 4
        for (int i = 0; i < 16; i++, m++) {
            __nv_bfloat16 rh = bfh(z.x), ih = bfh(z.y);
            AH[m * RSE + n]      = rh;
            AH[m * RSE + 64 + n] = ih;
            AL[m * RSE + n]      = bfh(z.x - __bfloat162float(rh));
            AL[m * RSE + 64 + n] = bfh(z.y - __bfloat162float(ih));
            z = cmul(z, w32);
        }
    }

    // B (U = cm*w^r, Im negated): q covers r in [8q, 8q+8)
    {
        float2 w1 = g_w1[pi];
        float2 z  = g_cm[pi];
        if (q & 1) z = cmul(z, g_w8[pi]);
        if (q & 2) z = cmul(z, g_w16[pi]);
        int r = q * 8;
#pragma unroll 4
        for (int i = 0; i < 8; i++, r++) {
            float vim = -z.y;
            __nv_bfloat16 rh = bfh(z.x), ih = bfh(vim);
            BH[r * RSE + n]      = rh;
            BH[r * RSE + 64 + n] = ih;
            BL[r * RSE + n]      = bfh(z.x - __bfloat162float(rh));
            BL[r * RSE + 64 + n] = bfh(vim - __bfloat162float(ih));
            z = cmul(z, w1);
        }
    }
    __syncthreads();

    // ---- MMA: warp = (m-tile mt, n-half nh); each warp 2 n-tiles ----
    const int mt = wid & 3, nh = wid >> 2;
    const int g8 = lane >> 3, l8 = lane & 7;

    const u32 aRow = (u32)(mt * 16 + (g8 & 1) * 8 + l8);
    const u32 aCol = (u32)((g8 >> 1) * 16);
    const u32 aH = sb + OFF_AH + aRow * 272u + aCol;
    const u32 aL = sb + OFF_AL + aRow * 272u + aCol;

    const u32 bRow = (u32)(nh * 16 + (g8 >> 1) * 8 + l8);
    const u32 bCol = (u32)((g8 & 1) * 16);
    const u32 bH = sb + OFF_BH + bRow * 272u + bCol;
    const u32 bL = sb + OFF_BL + bRow * 272u + bCol;

    float d0[4] = {0,0,0,0}, d1[4] = {0,0,0,0};

#pragma unroll
    for (int s = 0; s < 8; s++) {
        const u32 ko = (u32)s * 32u;
        u32 ah[4], al[4], bh[4], bl[4];
        ldsm4(ah, aH + ko);
        ldsm4(al, aL + ko);
        ldsm4(bh, bH + ko);
        ldsm4(bl, bL + ko);
        mma_bf16(d0, ah, bh[0], bh[1]);
        mma_bf16(d1, ah, bh[2], bh[3]);
        mma_bf16(d0, al, bh[0], bh[1]);
        mma_bf16(d1, al, bh[2], bh[3]);
        mma_bf16(d0, ah, bl[0], bl[1]);
        mma_bf16(d1, ah, bl[2], bl[3]);
    }

    // ---- store D: out[h*2048 + m*32 + col] ----
    {
        const int lr = lane >> 2, lc = lane & 3;
        const int m0 = mt * 16 + lr;
        const int c0 = nh * 16 + lc * 2;
        float* o = out + (size_t)h * 2048;
        *(float2*)(o + (m0    ) * 32 + c0    ) = make_float2(d0[0], d0[1]);
        *(float2*)(o + (m0 + 8) * 32 + c0    ) = make_float2(d0[2], d0[3]);
        *(float2*)(o + (m0    ) * 32 + c0 + 8) = make_float2(d1[0], d1[1]);
        *(float2*)(o + (m0 + 8) * 32 + c0 + 8) = make_float2(d1[2], d1[3]);
    }
}

extern "C" void kernel_launch(void* const* d_in, const int* in_sizes, int n_in,
                              void* d_out, int out_size)
{
    const float* log_dt = (const float*)d_in[0];
    const float* C      = (const float*)d_in[1];
    const float* A      = (const float*)d_in[2];

    int H = in_sizes[0];   // 1024

    cudaFuncSetAttribute(s4d_hmma, cudaFuncAttributeMaxDynamicSharedMemorySize,
                         SMEM_TOTAL);
    s4d_pre<<<(NPAR + 255) / 256, 256>>>(log_dt, C, A);
    s4d_hmma<<<H, 256, SMEM_TOTAL>>>((float*)d_out);
}

// round 15
// speedup vs baseline: 1.2618x; 1.2618x over previous
#include <cuda_runtime.h>
#include <cuda_bf16.h>
#include <cstdint>

// S4D via warp-level mma.sync bf16 (compute_103-safe).
// K[h, 32m + r] = Re( sum_n V[h,n,m] * U[h,n,r] ),
//   V = w32^m (m=0..63), U = cm*w^r (r=0..31), w = exp(dtA).
// Per h: D[64x32] = A[64x128] @ B[128x32]. K-dim interleaved: col 2n = Re,
// col 2n+1 = Im (B Im negated) -> staging stores are packed bf16x2 STS.32.
// bf16 2-way operand split, 3 products (AhBh + AlBh + AhBl), fp32 accum.
// Single fused kernel: light inline prologue (2 expf + 1 sincosf + squaring
// chain, threads 0..63) -> smem params -> staging recurrences -> MMA.

#define RSE    136                   // tile row stride in bf16 elems (272 B)
#define OFF_CM    0
#define OFF_W1    512
#define OFF_W8    1024
#define OFF_W16   1536
#define OFF_W32   2048
#define OFF_W512  2560
#define OFF_W1024 3072
#define OFF_AH    3584              // 64 x 272B = 17408
#define OFF_AL    (OFF_AH + 17408)
#define OFF_BH    (OFF_AL + 17408)  // 32 x 272B = 8704
#define OFF_BL    (OFF_BH + 8704)
#define SMEM_TOTAL (OFF_BL + 8704)  // 55808

typedef uint32_t u32;

__device__ __forceinline__ float2 cmul(float2 a, float2 b) {
    return make_float2(a.x * b.x - a.y * b.y, a.x * b.y + a.y * b.x);
}
__device__ __forceinline__ u32 smem_u32(const void* p) {
    u32 a;
    asm("{ .reg .u64 t; cvta.to.shared.u64 t, %1; cvt.u32.u64 %0, t; }"
        : "=r"(a) : "l"(p));
    return a;
}
__device__ __forceinline__ void ldsm4(u32 r[4], u32 addr) {
    asm volatile("ldmatrix.sync.aligned.m8n8.x4.shared.b16 {%0,%1,%2,%3}, [%4];"
                 : "=r"(r[0]), "=r"(r[1]), "=r"(r[2]), "=r"(r[3]) : "r"(addr));
}
__device__ __forceinline__ void mma_bf16(float d[4], const u32 a[4],
                                         u32 b0, u32 b1) {
    asm volatile(
        "mma.sync.aligned.m16n8k16.row.col.f32.bf16.bf16.f32 "
        "{%0,%1,%2,%3}, {%4,%5,%6,%7}, {%8,%9}, {%0,%1,%2,%3};"
        : "+f"(d[0]), "+f"(d[1]), "+f"(d[2]), "+f"(d[3])
        : "r"(a[0]), "r"(a[1]), "r"(a[2]), "r"(a[3]), "r"(b0), "r"(b1));
}
// pack (lo, hi) floats -> bf16x2 u32 (lo in low half = lower address)
__device__ __forceinline__ u32 pk(float lo, float hi) {
    __nv_bfloat162 t = __floats2bfloat162_rn(lo, hi);
    return *(u32*)&t;
}
__device__ __forceinline__ float2 residual(u32 packed, float lo, float hi) {
    __nv_bfloat162 t = *(__nv_bfloat162*)&packed;
    return make_float2(lo - __bfloat162float(t.x), hi - __bfloat162float(t.y));
}

extern "C" __global__ void __launch_bounds__(256)
s4d_hmma(const float* __restrict__ log_dt, const float* __restrict__ C,
         const float* __restrict__ A, float* __restrict__ out)
{
    extern __shared__ __align__(256) char sm[];
    const u32 sb  = smem_u32(sm);
    const int tid = threadIdx.x, wid = tid >> 5, lane = tid & 31;
    const int h   = blockIdx.x;

    float2* s_cm    = (float2*)(sm + OFF_CM);
    float2* s_w1    = (float2*)(sm + OFF_W1);
    float2* s_w8    = (float2*)(sm + OFF_W8);
    float2* s_w16   = (float2*)(sm + OFF_W16);
    float2* s_w32   = (float2*)(sm + OFF_W32);
    float2* s_w512  = (float2*)(sm + OFF_W512);
    float2* s_w1024 = (float2*)(sm + OFF_W1024);

    // ---- light prologue (threads 0..63): 2 expf + 1 sincosf + squarings ----
    if (tid < 64) {
        int n = tid;
        float dt  = expf(log_dt[h]);
        float ar  = A[2 * n], ai = A[2 * n + 1];
        float dre = dt * ar, dim = dt * ai;

        float e1 = expf(dre); float s1, c1; sincosf(dim, &s1, &c1);
        float2 w1 = make_float2(e1 * c1, e1 * s1);

        float inv = 1.0f / (ar * ar + ai * ai);
        float nr = w1.x - 1.0f, ni = w1.y;
        float qdr = (nr * ar + ni * ai) * inv;
        float qdi = (ni * ar - nr * ai) * inv;
        float cr = C[2 * (h * 64 + n)], ci = C[2 * (h * 64 + n) + 1];
        s_cm[n] = make_float2(2.0f * (cr * qdr - ci * qdi),
                              2.0f * (cr * qdi + ci * qdr));
        s_w1[n] = w1;

        float2 w2   = cmul(w1, w1);
        float2 w4   = cmul(w2, w2);
        float2 w8   = cmul(w4, w4);
        float2 w16  = cmul(w8, w8);
        float2 w32  = cmul(w16, w16);
        float2 w64  = cmul(w32, w32);
        float2 w128 = cmul(w64, w64);
        float2 w256 = cmul(w128, w128);
        float2 w512 = cmul(w256, w256);
        s_w8[n]    = w8;
        s_w16[n]   = w16;
        s_w32[n]   = w32;
        s_w512[n]  = w512;
        s_w1024[n] = cmul(w512, w512);
    }
    __syncthreads();

    // ---- staging: thread = (n, quarter q); packed Re/Im bf16x2 stores ----
    const int n = tid & 63, q = tid >> 6;

    // A (V = w32^m): q covers m in [16q, 16q+16); col pair (2n, 2n+1)
    {
        float2 w32 = s_w32[n];
        float2 z = make_float2(1.0f, 0.0f);
        if (q & 1) z = s_w512[n];
        if (q & 2) z = (q & 1) ? cmul(s_w512[n], s_w1024[n]) : s_w1024[n];
        u32 ah = sb + OFF_AH + (u32)(q * 16) * 272u + (u32)n * 4u;
        u32 al = sb + OFF_AL + (u32)(q * 16) * 272u + (u32)n * 4u;
#pragma unroll 4
        for (int i = 0; i < 16; i++) {
            u32 hi = pk(z.x, z.y);
            float2 rs = residual(hi, z.x, z.y);
            u32 lo = pk(rs.x, rs.y);
            asm volatile("st.shared.b32 [%0], %1;" :: "r"(ah), "r"(hi) : "memory");
            asm volatile("st.shared.b32 [%0], %1;" :: "r"(al), "r"(lo) : "memory");
            ah += 272u; al += 272u;
            z = cmul(z, w32);
        }
    }

    // B (U = cm*w^r, Im negated): q covers r in [8q, 8q+8)
    {
        float2 w1 = s_w1[n];
        float2 z  = s_cm[n];
        if (q & 1) z = cmul(z, s_w8[n]);
        if (q & 2) z = cmul(z, s_w16[n]);
        u32 bh = sb + OFF_BH + (u32)(q * 8) * 272u + (u32)n * 4u;
        u32 bl = sb + OFF_BL + (u32)(q * 8) * 272u + (u32)n * 4u;
#pragma unroll 4
        for (int i = 0; i < 8; i++) {
            float vim = -z.y;
            u32 hi = pk(z.x, vim);
            float2 rs = residual(hi, z.x, vim);
            u32 lo = pk(rs.x, rs.y);
            asm volatile("st.shared.b32 [%0], %1;" :: "r"(bh), "r"(hi) : "memory");
            asm volatile("st.shared.b32 [%0], %1;" :: "r"(bl), "r"(lo) : "memory");
            bh += 272u; bl += 272u;
            z = cmul(z, w1);
        }
    }
    __syncthreads();

    // ---- MMA: warp = (m-tile mt, n-half nh); each warp 2 n-tiles ----
    const int mt = wid & 3, nh = wid >> 2;
    const int g8 = lane >> 3, l8 = lane & 7;

    const u32 aRow = (u32)(mt * 16 + (g8 & 1) * 8 + l8);
    const u32 aCol = (u32)((g8 >> 1) * 16);
    const u32 aH = sb + OFF_AH + aRow * 272u + aCol;
    const u32 aL = sb + OFF_AL + aRow * 272u + aCol;

    const u32 bRow = (u32)(nh * 16 + (g8 >> 1) * 8 + l8);
    const u32 bCol = (u32)((g8 & 1) * 16);
    const u32 bH = sb + OFF_BH + bRow * 272u + bCol;
    const u32 bL = sb + OFF_BL + bRow * 272u + bCol;

    float d0[4] = {0,0,0,0}, d1[4] = {0,0,0,0};

#pragma unroll
    for (int s = 0; s < 8; s++) {
        const u32 ko = (u32)s * 32u;
        u32 ah[4], al[4], bh[4], bl[4];
        ldsm4(ah, aH + ko);
        ldsm4(al, aL + ko);
        ldsm4(bh, bH + ko);
        ldsm4(bl, bL + ko);
        mma_bf16(d0, ah, bh[0], bh[1]);
        mma_bf16(d1, ah, bh[2], bh[3]);
        mma_bf16(d0, al, bh[0], bh[1]);
        mma_bf16(d1, al, bh[2], bh[3]);
        mma_bf16(d0, ah, bl[0], bl[1]);
        mma_bf16(d1, ah, bl[2], bl[3]);
    }

    // ---- store D: out[h*2048 + m*32 + col] ----
    {
        const int lr = lane >> 2, lc = lane & 3;
        const int m0 = mt * 16 + lr;
        const int c0 = nh * 16 + lc * 2;
        float* o = out + (size_t)h * 2048;
        *(float2*)(o + (m0    ) * 32 + c0    ) = make_float2(d0[0], d0[1]);
        *(float2*)(o + (m0 + 8) * 32 + c0    ) = make_float2(d0[2], d0[3]);
        *(float2*)(o + (m0    ) * 32 + c0 + 8) = make_float2(d1[0], d1[1]);
        *(float2*)(o + (m0 + 8) * 32 + c0 + 8) = make_float2(d1[2], d1[3]);
    }
}

extern "C" void kernel_launch(void* const* d_in, const int* in_sizes, int n_in,
                              void* d_out, int out_size)
{
    const float* log_dt = (const float*)d_in[0];
    const float* C      = (const float*)d_in[1];
    const float* A      = (const float*)d_in[2];

    int H = in_sizes[0];   // 1024

    cudaFuncSetAttribute(s4d_hmma, cudaFuncAttributeMaxDynamicSharedMemorySize,
                         SMEM_TOTAL);
    s4d_hmma<<<H, 256, SMEM_TOTAL>>>(log_dt, C, A, (float*)d_out);
}

// round 16
// speedup vs baseline: 1.5923x; 1.2619x over previous
#include <cuda_runtime.h>
#include <cuda_fp16.h>
#include <cstdint>

// S4D via warp-level mma.sync fp16 (compute_103-safe).
// K[h, 32m + r] = Re( sum_n V[h,n,m] * U[h,n,r] ),
//   V = w32^m (m=0..63), U = cm*w^r (r=0..31), w = exp(dtA).
// Per h: D[64x32] = A[64x128] @ B[128x32]. K-dim interleaved: col 2n = Re,
// col 2n+1 = Im (B Im negated). SINGLE fp16 product (11-bit mantissa):
// quadrature rounding error ~2e-4 rel, inside the 1e-3 gate — no operand
// split needed. smem 29.7KB -> 7 blocks/SM -> all 1024 blocks in ONE wave.

#define RSE    136                   // tile row stride in fp16 elems (272 B)
#define OFF_CM    0
#define OFF_W1    512
#define OFF_W8    1024
#define OFF_W16   1536
#define OFF_W32   2048
#define OFF_W512  2560
#define OFF_W1024 3072
#define OFF_A     3584              // 64 x 272B = 17408
#define OFF_B     (OFF_A + 17408)   // 32 x 272B = 8704
#define SMEM_TOTAL (OFF_B + 8704)   // 29696

typedef uint32_t u32;

__device__ __forceinline__ float2 cmul(float2 a, float2 b) {
    return make_float2(a.x * b.x - a.y * b.y, a.x * b.y + a.y * b.x);
}
__device__ __forceinline__ u32 smem_u32(const void* p) {
    u32 a;
    asm("{ .reg .u64 t; cvta.to.shared.u64 t, %1; cvt.u32.u64 %0, t; }"
        : "=r"(a) : "l"(p));
    return a;
}
__device__ __forceinline__ void ldsm4(u32 r[4], u32 addr) {
    asm volatile("ldmatrix.sync.aligned.m8n8.x4.shared.b16 {%0,%1,%2,%3}, [%4];"
                 : "=r"(r[0]), "=r"(r[1]), "=r"(r[2]), "=r"(r[3]) : "r"(addr));
}
__device__ __forceinline__ void mma_f16(float d[4], const u32 a[4],
                                        u32 b0, u32 b1) {
    asm volatile(
        "mma.sync.aligned.m16n8k16.row.col.f32.f16.f16.f32 "
        "{%0,%1,%2,%3}, {%4,%5,%6,%7}, {%8,%9}, {%0,%1,%2,%3};"
        : "+f"(d[0]), "+f"(d[1]), "+f"(d[2]), "+f"(d[3])
        : "r"(a[0]), "r"(a[1]), "r"(a[2]), "r"(a[3]), "r"(b0), "r"(b1));
}
__device__ __forceinline__ u32 pk(float lo, float hi) {
    __half2 t = __floats2half2_rn(lo, hi);
    return *(u32*)&t;
}

extern "C" __global__ void __launch_bounds__(256, 7)
s4d_hmma(const float* __restrict__ log_dt, const float* __restrict__ C,
         const float* __restrict__ A, float* __restrict__ out)
{
    extern __shared__ __align__(256) char sm[];
    const u32 sb  = smem_u32(sm);
    const int tid = threadIdx.x, wid = tid >> 5, lane = tid & 31;
    const int h   = blockIdx.x;

    float2* s_cm    = (float2*)(sm + OFF_CM);
    float2* s_w1    = (float2*)(sm + OFF_W1);
    float2* s_w8    = (float2*)(sm + OFF_W8);
    float2* s_w16   = (float2*)(sm + OFF_W16);
    float2* s_w32   = (float2*)(sm + OFF_W32);
    float2* s_w512  = (float2*)(sm + OFF_W512);
    float2* s_w1024 = (float2*)(sm + OFF_W1024);

    // ---- light prologue (threads 0..63): 2 expf + 1 sincosf + squarings ----
    if (tid < 64) {
        int n = tid;
        float dt  = expf(log_dt[h]);
        float ar  = A[2 * n], ai = A[2 * n + 1];
        float dre = dt * ar, dim = dt * ai;

        float e1 = expf(dre); float s1, c1; sincosf(dim, &s1, &c1);
        float2 w1 = make_float2(e1 * c1, e1 * s1);

        float inv = 1.0f / (ar * ar + ai * ai);
        float nr = w1.x - 1.0f, ni = w1.y;
        float qdr = (nr * ar + ni * ai) * inv;
        float qdi = (ni * ar - nr * ai) * inv;
        float cr = C[2 * (h * 64 + n)], ci = C[2 * (h * 64 + n) + 1];
        s_cm[n] = make_float2(2.0f * (cr * qdr - ci * qdi),
                              2.0f * (cr * qdi + ci * qdr));
        s_w1[n] = w1;

        float2 w2   = cmul(w1, w1);
        float2 w4   = cmul(w2, w2);
        float2 w8   = cmul(w4, w4);
        float2 w16  = cmul(w8, w8);
        float2 w32  = cmul(w16, w16);
        float2 w64  = cmul(w32, w32);
        float2 w128 = cmul(w64, w64);
        float2 w256 = cmul(w128, w128);
        float2 w512 = cmul(w256, w256);
        s_w8[n]    = w8;
        s_w16[n]   = w16;
        s_w32[n]   = w32;
        s_w512[n]  = w512;
        s_w1024[n] = cmul(w512, w512);
    }
    __syncthreads();

    // ---- staging: thread = (n, quarter q); packed Re/Im fp16x2 stores ----
    const int n = tid & 63, q = tid >> 6;

    // A (V = w32^m): q covers m in [16q, 16q+16); col pair (2n, 2n+1)
    {
        float2 w32 = s_w32[n];
        float2 z = make_float2(1.0f, 0.0f);
        if (q & 1) z = s_w512[n];
        if (q & 2) z = (q & 1) ? cmul(s_w512[n], s_w1024[n]) : s_w1024[n];
        u32 ap = sb + OFF_A + (u32)(q * 16) * 272u + (u32)n * 4u;
#pragma unroll 4
        for (int i = 0; i < 16; i++) {
            u32 v = pk(z.x, z.y);
            asm volatile("st.shared.b32 [%0], %1;" :: "r"(ap), "r"(v) : "memory");
            ap += 272u;
            z = cmul(z, w32);
        }
    }

    // B (U = cm*w^r, Im negated): q covers r in [8q, 8q+8)
    {
        float2 w1 = s_w1[n];
        float2 z  = s_cm[n];
        if (q & 1) z = cmul(z, s_w8[n]);
        if (q & 2) z = cmul(z, s_w16[n]);
        u32 bp = sb + OFF_B + (u32)(q * 8) * 272u + (u32)n * 4u;
#pragma unroll 4
        for (int i = 0; i < 8; i++) {
            u32 v = pk(z.x, -z.y);
            asm volatile("st.shared.b32 [%0], %1;" :: "r"(bp), "r"(v) : "memory");
            bp += 272u;
            z = cmul(z, w1);
        }
    }
    __syncthreads();

    // ---- MMA: warp = (m-tile mt, n-half nh); each warp 2 n-tiles ----
    const int mt = wid & 3, nh = wid >> 2;
    const int g8 = lane >> 3, l8 = lane & 7;

    const u32 aRow = (u32)(mt * 16 + (g8 & 1) * 8 + l8);
    const u32 aCol = (u32)((g8 >> 1) * 16);
    const u32 aP = sb + OFF_A + aRow * 272u + aCol;

    const u32 bRow = (u32)(nh * 16 + (g8 >> 1) * 8 + l8);
    const u32 bCol = (u32)((g8 & 1) * 16);
    const u32 bP = sb + OFF_B + bRow * 272u + bCol;

    float d0[4] = {0,0,0,0}, d1[4] = {0,0,0,0};

#pragma unroll
    for (int s = 0; s < 8; s++) {
        const u32 ko = (u32)s * 32u;
        u32 a4[4], b4[4];
        ldsm4(a4, aP + ko);
        ldsm4(b4, bP + ko);
        mma_f16(d0, a4, b4[0], b4[1]);
        mma_f16(d1, a4, b4[2], b4[3]);
    }

    // ---- store D: out[h*2048 + m*32 + col] ----
    {
        const int lr = lane >> 2, lc = lane & 3;
        const int m0 = mt * 16 + lr;
        const int c0 = nh * 16 + lc * 2;
        float* o = out + (size_t)h * 2048;
        *(float2*)(o + (m0    ) * 32 + c0    ) = make_float2(d0[0], d0[1]);
        *(float2*)(o + (m0 + 8) * 32 + c0    ) = make_float2(d0[2], d0[3]);
        *(float2*)(o + (m0    ) * 32 + c0 + 8) = make_float2(d1[0], d1[1]);
        *(float2*)(o + (m0 + 8) * 32 + c0 + 8) = make_float2(d1[2], d1[3]);
    }
}

extern "C" void kernel_launch(void* const* d_in, const int* in_sizes, int n_in,
                              void* d_out, int out_size)
{
    const float* log_dt = (const float*)d_in[0];
    const float* C      = (const float*)d_in[1];
    const float* A      = (const float*)d_in[2];

    int H = in_sizes[0];   // 1024

    cudaFuncSetAttribute(s4d_hmma, cudaFuncAttributeMaxDynamicSharedMemorySize,
                         SMEM_TOTAL);
    s4d_hmma<<<H, 256, SMEM_TOTAL>>>(log_dt, C, A, (float*)d_out);
}

// round 17
// speedup vs baseline: 1.5970x; 1.0030x over previous
#include <cuda_runtime.h>
#include <cuda_fp16.h>
#include <cstdint>

// S4D via warp-level mma.sync fp16 (compute_103-safe).
// K[h, 32m + r] = Re( sum_n V[h,n,m] * U[h,n,r] ),
//   V = w32^m (m=0..63), U = cm*w^r (r=0..31), w = exp(dtA).
// Per h: D[64x32] = A[64x128] @ B[128x32]. K-dim interleaved: col 2n = Re,
// col 2n+1 = Im (B Im negated). Single fp16 product (rel_err ~2e-4).
// smem ~30KB -> 7 blocks/SM -> all 1024 blocks in ONE wave.
// R17: staging recurrences split into 2 independent chains per thread
// (A steps w64 over even/odd m; B steps w2 over even/odd r) -> half the
// serial RAW chain, ~2x staging issue density.

#define OFF_CM    0
#define OFF_W1    512
#define OFF_W2    1024
#define OFF_W8    1536
#define OFF_W16   2048
#define OFF_W32   2560
#define OFF_W64   3072
#define OFF_W512  3584
#define OFF_W1024 4096
#define OFF_A     4608              // 64 x 272B = 17408
#define OFF_B     (OFF_A + 17408)   // 32 x 272B = 8704
#define SMEM_TOTAL (OFF_B + 8704)   // 30720

typedef uint32_t u32;

__device__ __forceinline__ float2 cmul(float2 a, float2 b) {
    return make_float2(a.x * b.x - a.y * b.y, a.x * b.y + a.y * b.x);
}
__device__ __forceinline__ u32 smem_u32(const void* p) {
    u32 a;
    asm("{ .reg .u64 t; cvta.to.shared.u64 t, %1; cvt.u32.u64 %0, t; }"
        : "=r"(a) : "l"(p));
    return a;
}
__device__ __forceinline__ void ldsm4(u32 r[4], u32 addr) {
    asm volatile("ldmatrix.sync.aligned.m8n8.x4.shared.b16 {%0,%1,%2,%3}, [%4];"
                 : "=r"(r[0]), "=r"(r[1]), "=r"(r[2]), "=r"(r[3]) : "r"(addr));
}
__device__ __forceinline__ void mma_f16(float d[4], const u32 a[4],
                                        u32 b0, u32 b1) {
    asm volatile(
        "mma.sync.aligned.m16n8k16.row.col.f32.f16.f16.f32 "
        "{%0,%1,%2,%3}, {%4,%5,%6,%7}, {%8,%9}, {%0,%1,%2,%3};"
        : "+f"(d[0]), "+f"(d[1]), "+f"(d[2]), "+f"(d[3])
        : "r"(a[0]), "r"(a[1]), "r"(a[2]), "r"(a[3]), "r"(b0), "r"(b1));
}
__device__ __forceinline__ u32 pk(float lo, float hi) {
    __half2 t = __floats2half2_rn(lo, hi);
    return *(u32*)&t;
}
__device__ __forceinline__ void sts32(u32 addr, u32 v) {
    asm volatile("st.shared.b32 [%0], %1;" :: "r"(addr), "r"(v) : "memory");
}

extern "C" __global__ void __launch_bounds__(256, 7)
s4d_hmma(const float* __restrict__ log_dt, const float* __restrict__ C,
         const float* __restrict__ A, float* __restrict__ out)
{
    extern __shared__ __align__(256) char sm[];
    const u32 sb  = smem_u32(sm);
    const int tid = threadIdx.x, wid = tid >> 5, lane = tid & 31;
    const int h   = blockIdx.x;

    float2* s_cm    = (float2*)(sm + OFF_CM);
    float2* s_w1    = (float2*)(sm + OFF_W1);
    float2* s_w2    = (float2*)(sm + OFF_W2);
    float2* s_w8    = (float2*)(sm + OFF_W8);
    float2* s_w16   = (float2*)(sm + OFF_W16);
    float2* s_w32   = (float2*)(sm + OFF_W32);
    float2* s_w64   = (float2*)(sm + OFF_W64);
    float2* s_w512  = (float2*)(sm + OFF_W512);
    float2* s_w1024 = (float2*)(sm + OFF_W1024);

    // ---- light prologue (threads 0..63): 2 expf + 1 sincosf + squarings ----
    if (tid < 64) {
        int n = tid;
        float dt  = expf(log_dt[h]);
        float ar  = A[2 * n], ai = A[2 * n + 1];
        float dre = dt * ar, dim = dt * ai;

        float e1 = expf(dre); float s1, c1; sincosf(dim, &s1, &c1);
        float2 w1 = make_float2(e1 * c1, e1 * s1);

        float inv = 1.0f / (ar * ar + ai * ai);
        float nr = w1.x - 1.0f, ni = w1.y;
        float qdr = (nr * ar + ni * ai) * inv;
        float qdi = (ni * ar - nr * ai) * inv;
        float cr = C[2 * (h * 64 + n)], ci = C[2 * (h * 64 + n) + 1];
        s_cm[n] = make_float2(2.0f * (cr * qdr - ci * qdi),
                              2.0f * (cr * qdi + ci * qdr));
        s_w1[n] = w1;

        float2 w2   = cmul(w1, w1);
        float2 w4   = cmul(w2, w2);
        float2 w8   = cmul(w4, w4);
        float2 w16  = cmul(w8, w8);
        float2 w32  = cmul(w16, w16);
        float2 w64  = cmul(w32, w32);
        float2 w128 = cmul(w64, w64);
        float2 w256 = cmul(w128, w128);
        float2 w512 = cmul(w256, w256);
        s_w2[n]    = w2;
        s_w8[n]    = w8;
        s_w16[n]   = w16;
        s_w32[n]   = w32;
        s_w64[n]   = w64;
        s_w512[n]  = w512;
        s_w1024[n] = cmul(w512, w512);
    }
    __syncthreads();

    // ---- staging: thread = (n, quarter q); 2 independent chains each ----
    const int n = tid & 63, q = tid >> 6;

    // A (V = w32^m): q covers m in [16q, 16q+16); even/odd chains step w64
    {
        float2 w64 = s_w64[n];
        float2 za = make_float2(1.0f, 0.0f);
        if (q & 1) za = s_w512[n];
        if (q & 2) za = (q & 1) ? cmul(s_w512[n], s_w1024[n]) : s_w1024[n];
        float2 zb = cmul(za, s_w32[n]);
        u32 ap = sb + OFF_A + (u32)(q * 16) * 272u + (u32)n * 4u;
#pragma unroll
        for (int i = 0; i < 8; i++) {
            sts32(ap,        pk(za.x, za.y));
            sts32(ap + 272u, pk(zb.x, zb.y));
            ap += 544u;
            za = cmul(za, w64);
            zb = cmul(zb, w64);
        }
    }

    // B (U = cm*w^r, Im negated): q covers r in [8q, 8q+8); chains step w2
    {
        float2 w2 = s_w2[n];
        float2 za = s_cm[n];
        if (q & 1) za = cmul(za, s_w8[n]);
        if (q & 2) za = cmul(za, s_w16[n]);
        float2 zb = cmul(za, s_w1[n]);
        u32 bp = sb + OFF_B + (u32)(q * 8) * 272u + (u32)n * 4u;
#pragma unroll
        for (int i = 0; i < 4; i++) {
            sts32(bp,        pk(za.x, -za.y));
            sts32(bp + 272u, pk(zb.x, -zb.y));
            bp += 544u;
            za = cmul(za, w2);
            zb = cmul(zb, w2);
        }
    }
    __syncthreads();

    // ---- MMA: warp = (m-tile mt, n-half nh); each warp 2 n-tiles ----
    const int mt = wid & 3, nh = wid >> 2;
    const int g8 = lane >> 3, l8 = lane & 7;

    const u32 aRow = (u32)(mt * 16 + (g8 & 1) * 8 + l8);
    const u32 aCol = (u32)((g8 >> 1) * 16);
    const u32 aP = sb + OFF_A + aRow * 272u + aCol;

    const u32 bRow = (u32)(nh * 16 + (g8 >> 1) * 8 + l8);
    const u32 bCol = (u32)((g8 & 1) * 16);
    const u32 bP = sb + OFF_B + bRow * 272u + bCol;

    float d0[4] = {0,0,0,0}, d1[4] = {0,0,0,0};

#pragma unroll
    for (int s = 0; s < 8; s++) {
        const u32 ko = (u32)s * 32u;
        u32 a4[4], b4[4];
        ldsm4(a4, aP + ko);
        ldsm4(b4, bP + ko);
        mma_f16(d0, a4, b4[0], b4[1]);
        mma_f16(d1, a4, b4[2], b4[3]);
    }

    // ---- store D: out[h*2048 + m*32 + col] ----
    {
        const int lr = lane >> 2, lc = lane & 3;
        const int m0 = mt * 16 + lr;
        const int c0 = nh * 16 + lc * 2;
        float* o = out + (size_t)h * 2048;
        *(float2*)(o + (m0    ) * 32 + c0    ) = make_float2(d0[0], d0[1]);
        *(float2*)(o + (m0 + 8) * 32 + c0    ) = make_float2(d0[2], d0[3]);
        *(float2*)(o + (m0    ) * 32 + c0 + 8) = make_float2(d1[0], d1[1]);
        *(float2*)(o + (m0 + 8) * 32 + c0 + 8) = make_float2(d1[2], d1[3]);
    }
}

extern "C" void kernel_launch(void* const* d_in, const int* in_sizes, int n_in,
                              void* d_out, int out_size)
{
    const float* log_dt = (const float*)d_in[0];
    const float* C      = (const float*)d_in[1];
    const float* A      = (const float*)d_in[2];

    int H = in_sizes[0];   // 1024

    cudaFuncSetAttribute(s4d_hmma, cudaFuncAttributeMaxDynamicSharedMemorySize,
                         SMEM_TOTAL);
    s4d_hmma<<<H, 256, SMEM_TOTAL>>>(log_dt, C, A, (float*)d_out);
}